// round 1
// baseline (speedup 1.0000x reference)
#include <cuda_runtime.h>

// Problem constants (fixed by the dataset)
#define N_NODES_MAX 50000
#define E_MAX       550000
#define B_MAX       4096
#define F           128
#define H           512

// Scratch (static device globals — no allocation allowed)
__device__ int   g_flag[N_NODES_MAX];     // 0 = unmarked, else slot+1
__device__ int   g_deg[B_MAX];            // in-degree per slot
__device__ float g_accum[B_MAX * F];      // neighbor feature sums per slot
__device__ int   g_count;                 // active-edge count
__device__ int   g_esrc[E_MAX];           // compacted active edges: src node
__device__ int   g_eslot[E_MAX];          // compacted active edges: dst slot
__device__ float g_h[B_MAX * F];          // dense h_neigh rows for the GEMM

// ---------------------------------------------------------------------------
// K0: reset all scratch touched this launch
__global__ void k_reset(int n_nodes) {
    int i = blockIdx.x * blockDim.x + threadIdx.x;
    int stride = gridDim.x * blockDim.x;
    for (int idx = i; idx < B_MAX * F; idx += stride) g_accum[idx] = 0.0f;
    for (int idx = i; idx < n_nodes; idx += stride) g_flag[idx] = 0;
    for (int idx = i; idx < B_MAX; idx += stride) g_deg[idx] = 0;
    if (i == 0) g_count = 0;
}

// K1: mark id nodes with their slot (+1). Duplicate ids: arbitrary winner,
// but all subsequent readers use the same winner, so result is consistent.
__global__ void k_mark(const int* __restrict__ ids, int nb) {
    int i = blockIdx.x * blockDim.x + threadIdx.x;
    if (i < nb) g_flag[ids[i]] = i + 1;
}

// K2: scan all edges; count degree and compact edges landing on marked nodes
__global__ void k_scan(const int* __restrict__ src, const int* __restrict__ dst, int ne) {
    int i = blockIdx.x * blockDim.x + threadIdx.x;
    if (i >= ne) return;
    int d = dst[i];
    int f = g_flag[d];
    if (f > 0) {
        int slot = f - 1;
        atomicAdd(&g_deg[slot], 1);
        int idx = atomicAdd(&g_count, 1);
        g_esrc[idx]  = src[i];
        g_eslot[idx] = slot;
    }
}

// K3: warp per active edge; scatter-add feat[src] into accum[slot]
__global__ void k_scatter(const float* __restrict__ feat) {
    int gtid  = blockIdx.x * blockDim.x + threadIdx.x;
    int warp  = gtid >> 5;
    int lane  = threadIdx.x & 31;
    int nwarp = (gridDim.x * blockDim.x) >> 5;
    int cnt = g_count;
    for (int e = warp; e < cnt; e += nwarp) {
        int s    = g_esrc[e];
        int slot = g_eslot[e];
        const float4* fr = (const float4*)(feat + (size_t)s * F);
        float* acc = g_accum + (size_t)slot * F;
        float4 v = fr[lane];            // 32 lanes x float4 = 128 floats
        atomicAdd(acc + lane * 4 + 0, v.x);
        atomicAdd(acc + lane * 4 + 1, v.y);
        atomicAdd(acc + lane * 4 + 2, v.z);
        atomicAdd(acc + lane * 4 + 3, v.w);
    }
}

// K4: h_neigh rows for each output index: (neigh_sum + feat[v]) / (deg + 1)
__global__ void k_h(const float* __restrict__ feat, const int* __restrict__ ids, int nb) {
    int idx = blockIdx.x * blockDim.x + threadIdx.x;
    if (idx >= nb * F) return;
    int i = idx >> 7;          // output row
    int k = idx & (F - 1);     // feature
    int node = ids[i];
    int slot = g_flag[node] - 1;
    float inv = 1.0f / (float)(g_deg[slot] + 1);
    g_h[idx] = (g_accum[(size_t)slot * F + k] + feat[(size_t)node * F + k]) * inv;
}

// K5: out[i][j] = tanh( sum_k h[i][k] * W[j][k] + bias[j] )
// M=nb(4096), N=H(512), K=F(128). BM=BN=64, BK=32, 4x4 per-thread tile.
__global__ void k_gemm(const float* __restrict__ W, const float* __restrict__ bias,
                       float* __restrict__ out) {
    __shared__ float As[32][65];
    __shared__ float Bs[32][65];

    int tx = threadIdx.x & 15;   // 0..15 -> cols
    int ty = threadIdx.x >> 4;   // 0..15 -> rows
    int rowBase = blockIdx.y * 64;
    int colBase = blockIdx.x * 64;

    float acc[4][4];
    #pragma unroll
    for (int i = 0; i < 4; i++)
        #pragma unroll
        for (int j = 0; j < 4; j++) acc[i][j] = 0.0f;

    for (int k0 = 0; k0 < F; k0 += 32) {
        // 64 rows x 32 cols per tile = 512 float4; 256 threads x 2
        #pragma unroll
        for (int l = 0; l < 2; l++) {
            int t  = threadIdx.x + l * 256;
            int r  = t >> 3;      // 0..63
            int c4 = t & 7;       // 0..7
            float4 v = *(const float4*)(g_h + (size_t)(rowBase + r) * F + k0 + c4 * 4);
            As[c4 * 4 + 0][r] = v.x;
            As[c4 * 4 + 1][r] = v.y;
            As[c4 * 4 + 2][r] = v.z;
            As[c4 * 4 + 3][r] = v.w;
            float4 w = *(const float4*)(W + (size_t)(colBase + r) * F + k0 + c4 * 4);
            Bs[c4 * 4 + 0][r] = w.x;
            Bs[c4 * 4 + 1][r] = w.y;
            Bs[c4 * 4 + 2][r] = w.z;
            Bs[c4 * 4 + 3][r] = w.w;
        }
        __syncthreads();

        #pragma unroll
        for (int kk = 0; kk < 32; kk++) {
            float a[4], b[4];
            #pragma unroll
            for (int i = 0; i < 4; i++) a[i] = As[kk][ty * 4 + i];
            #pragma unroll
            for (int j = 0; j < 4; j++) b[j] = Bs[kk][tx * 4 + j];
            #pragma unroll
            for (int i = 0; i < 4; i++)
                #pragma unroll
                for (int j = 0; j < 4; j++)
                    acc[i][j] += a[i] * b[j];
        }
        __syncthreads();
    }

    #pragma unroll
    for (int i = 0; i < 4; i++) {
        int r = rowBase + ty * 4 + i;
        #pragma unroll
        for (int j = 0; j < 4; j++) {
            int c = colBase + tx * 4 + j;
            out[(size_t)r * H + c] = tanhf(acc[i][j] + bias[c]);
        }
    }
}

// ---------------------------------------------------------------------------
extern "C" void kernel_launch(void* const* d_in, const int* in_sizes, int n_in,
                              void* d_out, int out_size) {
    const float* feat = (const float*)d_in[0];   // [N, 128]
    const float* W    = (const float*)d_in[1];   // [512, 128]
    const float* bias = (const float*)d_in[2];   // [512]
    const int*   src  = (const int*)d_in[3];     // [E]
    const int*   dst  = (const int*)d_in[4];     // [E]
    const int*   ids  = (const int*)d_in[5];     // [B]

    int n_nodes = in_sizes[0] / F;
    int ne      = in_sizes[3];
    int nb      = in_sizes[5];

    k_reset<<<256, 256>>>(n_nodes);
    k_mark<<<(nb + 255) / 256, 256>>>(ids, nb);
    k_scan<<<(ne + 255) / 256, 256>>>(src, dst, ne);
    k_scatter<<<512, 256>>>(feat);
    k_h<<<(nb * F + 255) / 256, 256>>>(feat, ids, nb);
    dim3 ggrid(H / 64, nb / 64);
    k_gemm<<<ggrid, 256>>>(W, bias, (float*)d_out);
}